// round 17
// baseline (speedup 1.0000x reference)
#include <cuda_runtime.h>
#include <cuda_bf16.h>

#define NFLAT 238144        // 64*61*61

// ---------------- scratch (device globals; no allocation) ----------------
__device__ __align__(128) float g_out1p[4 * 4096 * 32];
__device__ __align__(128) float g_pool[NFLAT];
__device__ __align__(128) float g_r128[128];
__device__ __align__(128) float g_E[128 * 256];    // D2 @ CK_bot
__device__ __align__(128) float g_qt_in[256];      // inputs @ CK_top
__device__ __align__(128) float g_st[256];
__device__ __align__(128) float g_rt[256];
__device__ __align__(128) float g_dp[512];         // d partials (2 halves)
__device__ __align__(128) float g_ct[256];
__device__ __align__(128) unsigned g_maxu;
__device__ __align__(128) float g_sumexp;
__device__ __align__(128) unsigned g_count;
__device__ __align__(128) unsigned g_sense;

// ---------------- packed fp32x2 helpers ----------------
typedef unsigned long long ull;
__device__ __forceinline__ ull pack2(float lo, float hi) {
    ull r; asm("mov.b64 %0, {%1,%2};" : "=l"(r) : "f"(lo), "f"(hi)); return r;
}
__device__ __forceinline__ void unpack2(ull v, float& lo, float& hi) {
    asm("mov.b64 {%0,%1}, %2;" : "=f"(lo), "=f"(hi) : "l"(v));
}
__device__ __forceinline__ void fma2(ull& d, ull a, ull b) {
    asm("fma.rn.f32x2 %0, %1, %2, %0;" : "+l"(d) : "l"(a), "l"(b));
}

// ---------------- ordered-uint float encode (for atomicMax) ----------------
__device__ __forceinline__ unsigned enc_f(float f) {
    unsigned b = __float_as_uint(f);
    return (b & 0x80000000u) ? ~b : (b | 0x80000000u);
}
__device__ __forceinline__ float dec_f(unsigned u) {
    return (u & 0x80000000u) ? __uint_as_float(u & 0x7FFFFFFFu) : __uint_as_float(~u);
}

// =========================================================================
// LAUNCH 1: conv1 (128) + transpose (256) + E (128) + st (1) + qt_in (1)
// =========================================================================
__global__ __launch_bounds__(256) void stage1_kernel(const float* __restrict__ mem,
                                                     const float* __restrict__ K1,
                                                     const float* __restrict__ D2,
                                                     const float* __restrict__ CK,
                                                     const float* __restrict__ REC,
                                                     const float* __restrict__ inp,
                                                     float* __restrict__ out) {
    __shared__ float sm[7360];
    int bid = blockIdx.x;
    int tid = threadIdx.x;

    if (bid < 128) {
        // ---- conv1: SAME 3x3, 256->32. 2 rows x 64 ic per block. 4px x 4oc/thread.
        float* sIn = sm;            // 2 halves x 32ic x 67 = 4288
        float* sW  = sm + 4288;     // 3kw x 32ic x 32oc = 3072
        int icq  = bid & 3;
        int h0   = (bid >> 2) * 2;
        int half = tid >> 7;
        int t    = tid & 127;
        int pg = t & 15, og = t >> 4;

        ull acc0[4] = {0ull,0ull,0ull,0ull};
        ull acc1[4] = {0ull,0ull,0ull,0ull};

        for (int kh = 0; kh < 3; kh++) {
            for (int ch = 0; ch < 2; ch++) {
                int ic0 = icq * 64 + ch * 32;
                __syncthreads();
                for (int t2 = tid; t2 < 4224; t2 += 256) {
                    int hh = (t2 >= 2112) ? 1 : 0;
                    int lc = t2 - hh * 2112;
                    int ic = lc & 31, c = lc >> 5;
                    int r = h0 + kh - 1 + hh;
                    int col = c - 1;
                    float v = 0.f;
                    if (r >= 0 && r < 64 && col >= 0 && col < 64)
                        v = mem[(r * 64 + col) * 256 + ic0 + ic];
                    sIn[hh * 2144 + ic * 67 + c] = v;
                }
                for (int t2 = tid; t2 < 3072; t2 += 256) {
                    int oc = t2 & 31, ic = (t2 >> 5) & 31, kw = t2 >> 10;
                    sW[t2] = K1[((kh * 3 + kw) * 256 + ic0 + ic) * 32 + oc];
                }
                __syncthreads();
                const float* base = sIn + half * 2144;
#pragma unroll 4
                for (int ic = 0; ic < 32; ic++) {
                    ull xb[6];
#pragma unroll
                    for (int c = 0; c < 6; c++) {
                        float x = base[ic * 67 + pg * 4 + c];
                        xb[c] = pack2(x, x);
                    }
#pragma unroll
                    for (int kw = 0; kw < 3; kw++) {
                        const ull* wp = (const ull*)&sW[(kw * 32 + ic) * 32 + og * 4];
                        ull w0 = wp[0], w1 = wp[1];
#pragma unroll
                        for (int a = 0; a < 4; a++) {
                            fma2(acc0[a], xb[a + kw], w0);
                            fma2(acc1[a], xb[a + kw], w1);
                        }
                    }
                }
            }
        }
        int row = h0 + half;
#pragma unroll
        for (int a = 0; a < 4; a++) {
            float l0, h1, l2, h3;
            unpack2(acc0[a], l0, h1);
            unpack2(acc1[a], l2, h3);
            *(float4*)&g_out1p[icq * 131072 + (row * 64 + pg * 4 + a) * 32 + og * 4] =
                make_float4(l0, h1, l2, h3);
        }
    } else if (bid < 384) {
        // ---- transpose memory -> out[512 + c*4096 + p]
        int tb = bid - 128;
        float* tile = sm;   // 128 x 33 = 4224
        int p0 = (tb >> 3) * 128;
        int c0 = (tb & 7) * 32;
        for (int t2 = tid; t2 < 4096; t2 += 256) {
            int p = t2 >> 5, c = t2 & 31;
            tile[p * 33 + c] = mem[(p0 + p) * 256 + c0 + c];
        }
        __syncthreads();
        for (int t2 = tid; t2 < 4096; t2 += 256) {
            int c = t2 >> 7, p = t2 & 127;
            out[512 + (long)(c0 + c) * 4096 + p0 + p] = tile[p * 33 + c];
        }
    } else if (bid < 512) {
        // ---- E row k: E[k][j] = sum_c D2[k][c] * CK[(128+c)][j]
        int k = bid - 384;
        float* d2r = sm;
        if (tid < 256) d2r[tid] = D2[k * 256 + tid];
        __syncthreads();
        float acc = 0.f;
#pragma unroll 16
        for (int c = 0; c < 256; c++) acc += d2r[c] * CK[(128 + c) * 256 + tid];
        g_E[k * 256 + tid] = acc;
    } else if (bid == 512) {
        // ---- st = inputs @ REC_top
        float* si = sm;
        if (tid < 128) si[tid] = inp[tid];
        __syncthreads();
        float acc = 0.f;
#pragma unroll 16
        for (int kk = 0; kk < 128; kk++) acc += si[kk] * REC[kk * 256 + tid];
        g_st[tid] = acc;
    } else {
        // ---- qt_in = inputs @ CK_top
        float* si = sm;
        if (tid < 128) si[tid] = inp[tid];
        __syncthreads();
        float acc = 0.f;
#pragma unroll 16
        for (int kk = 0; kk < 128; kk++) acc += si[kk] * CK[kk * 256 + tid];
        g_qt_in[tid] = acc;
    }
}

// =========================================================================
// LAUNCH 2: conv2 + pool (grid x 0..60) ; x==61 -> d partials ; (0,0) zero-init
// =========================================================================
__global__ __launch_bounds__(256) void conv2_kernel(const float* __restrict__ K2,
                                                    const float* __restrict__ REC,
                                                    const float* __restrict__ mem,
                                                    const int* __restrict__ xp,
                                                    const int* __restrict__ yp) {
    extern __shared__ float sm2[];
    int i    = blockIdx.x;
    int half = blockIdx.y;
    int tid  = threadIdx.x;

    if (i == 61) {
        // ---- d partial: d_half[j] = sum_{c in half} (mem_t[c]-st[c]) * REC[(128+c)][j]
        float* am = sm2;
        int pix = xp[0] * 64 + yp[0];
        int c0 = half * 128;
        if (tid < 128) am[tid] = mem[pix * 256 + c0 + tid] - g_st[c0 + tid];
        __syncthreads();
        float acc = 0.f;
#pragma unroll 16
        for (int u = 0; u < 128; u++) acc += am[u] * REC[(128 + c0 + u) * 256 + tid];
        g_dp[half * 256 + tid] = acc;
        return;
    }

    float* sIn = sm2;            // 4 rows x 32ic x 65 = 8320 (reused as sC[2][32][64])
    float* sW  = sm2 + 8320;     // 9*32*32 = 9216

    if (i == 0 && half == 0) {
        if (tid < 128) g_r128[tid] = 0.f;
        g_ct[tid] = 0.f;
        if (tid == 0) { g_maxu = 0u; g_sumexp = 0.f; }
    }

    for (int t = tid; t < 8192; t += 256) {
        int ic = t & 31, col = (t >> 5) & 63, rr = t >> 11;
        const float* p = g_out1p + ((i + rr) * 64 + col) * 32 + ic;
        sIn[(rr * 32 + ic) * 65 + col] = p[0] + p[131072] + p[262144] + p[393216];
    }
    for (int t = tid; t < 9216; t += 256) {
        int ocl = t & 31, ic = (t >> 5) & 31, kk = t >> 10;
        sW[t] = K2[(kk * 32 + ic) * 64 + half * 32 + ocl];
    }
    __syncthreads();

    int pxg = tid & 31, ocg = tid >> 5;
    ull acc[2][2][2];
#pragma unroll
    for (int r = 0; r < 2; r++)
#pragma unroll
        for (int a = 0; a < 2; a++)
#pragma unroll
            for (int b = 0; b < 2; b++) acc[r][a][b] = 0ull;

    int px = pxg * 2;
    if (pxg < 31) {
#pragma unroll
        for (int r = 0; r < 2; r++)
            for (int kh = 0; kh < 3; kh++) {
#pragma unroll 4
                for (int ic = 0; ic < 32; ic++) {
                    ull xb[4];
#pragma unroll
                    for (int c = 0; c < 4; c++) {
                        float x = sIn[((r + kh) * 32 + ic) * 65 + px + c];
                        xb[c] = pack2(x, x);
                    }
#pragma unroll
                    for (int kw = 0; kw < 3; kw++) {
                        const ull* wp = (const ull*)&sW[((kh * 3 + kw) * 32 + ic) * 32 + ocg * 4];
                        ull w0 = wp[0], w1 = wp[1];
                        fma2(acc[r][0][0], xb[kw + 0], w0);
                        fma2(acc[r][0][1], xb[kw + 0], w1);
                        fma2(acc[r][1][0], xb[kw + 1], w0);
                        fma2(acc[r][1][1], xb[kw + 1], w1);
                    }
                }
            }
    }
    __syncthreads();
    if (pxg < 31) {
#pragma unroll
        for (int r = 0; r < 2; r++)
#pragma unroll
            for (int b = 0; b < 2; b++) {
                float lo, hi;
                unpack2(acc[r][0][b], lo, hi);
                sIn[(r * 32 + ocg * 4 + b * 2 + 0) * 64 + px + 0] = lo;
                sIn[(r * 32 + ocg * 4 + b * 2 + 1) * 64 + px + 0] = hi;
                unpack2(acc[r][1][b], lo, hi);
                sIn[(r * 32 + ocg * 4 + b * 2 + 0) * 64 + px + 1] = lo;
                sIn[(r * 32 + ocg * 4 + b * 2 + 1) * 64 + px + 1] = hi;
            }
    }
    __syncthreads();
    for (int t = tid; t < 2048; t += 256) {
        int j = t & 63, ocl = t >> 6;
        if (j < 61) {
            float v = 0.25f * (sIn[ocl * 64 + j] + sIn[ocl * 64 + j + 1] +
                               sIn[(32 + ocl) * 64 + j] + sIn[(32 + ocl) * 64 + j + 1]);
            g_pool[(half * 32 + ocl) * 3721 + i * 61 + j] = v;
        }
    }
}

// =========================================================================
// LAUNCH 3: GEMV r128 += pool @ D1. 466 blocks, 8-deep float4 unroll.
// =========================================================================
__global__ __launch_bounds__(256) void gemv_kernel(const float* __restrict__ D1) {
    __shared__ float sp[512];
    __shared__ float red[8 * 128];
    int fbase = blockIdx.x * 512;
    int n = NFLAT - fbase; if (n > 512) n = 512;
    for (int t = threadIdx.x; t < 512; t += 256) sp[t] = (t < n) ? g_pool[fbase + t] : 0.f;
    __syncthreads();
    int kq = threadIdx.x & 31, slot = threadIdx.x >> 5;
    const float4* D1v = (const float4*)D1;
    float4 a4 = make_float4(0.f, 0.f, 0.f, 0.f);
    int rr = slot;
    for (; rr + 56 < n; rr += 64) {
        float4 d[8];
        float s[8];
#pragma unroll
        for (int u = 0; u < 8; u++) {
            s[u] = sp[rr + u * 8];
            d[u] = D1v[(long)(fbase + rr + u * 8) * 32 + kq];
        }
#pragma unroll
        for (int u = 0; u < 8; u++) {
            a4.x += s[u] * d[u].x; a4.y += s[u] * d[u].y;
            a4.z += s[u] * d[u].z; a4.w += s[u] * d[u].w;
        }
    }
    for (; rr < n; rr += 8) {
        float s = sp[rr];
        float4 dv = D1v[(long)(fbase + rr) * 32 + kq];
        a4.x += s * dv.x; a4.y += s * dv.y; a4.z += s * dv.z; a4.w += s * dv.w;
    }
    float* rp = &red[slot * 128 + kq * 4];
    rp[0] = a4.x; rp[1] = a4.y; rp[2] = a4.z; rp[3] = a4.w;
    __syncthreads();
    if (threadIdx.x < 128) {
        float v = 0.f;
#pragma unroll
        for (int s = 0; s < 8; s++) v += red[s * 128 + threadIdx.x];
        atomicAdd(&g_r128[threadIdx.x], v);
    }
}

// =========================================================================
// LAUNCH 4: tail. 128 blocks, 2 sense-reversal grid barriers.
// =========================================================================
__device__ __forceinline__ void gbar() {
    __syncthreads();
    if (threadIdx.x == 0) {
        __threadfence();
        unsigned s = *(volatile unsigned*)&g_sense;
        unsigned prev = atomicAdd(&g_count, 1u);
        if (prev == 127u) {
            g_count = 0u;
            __threadfence();
            atomicExch(&g_sense, s + 1u);
        } else {
            while (*(volatile unsigned*)&g_sense == s) __nanosleep(32);
        }
        __threadfence();
    }
    __syncthreads();
}

__global__ __launch_bounds__(256) void stage3_kernel(const float* __restrict__ mem,
                                                     const float* __restrict__ D2,
                                                     const int* __restrict__ xp,
                                                     const int* __restrict__ yp,
                                                     float* __restrict__ out) {
    __shared__ float sRow[32 * 256];   // this block's 32 memory rows (32KB)
    __shared__ float qs[256];
    __shared__ float r128s[128];
    __shared__ float scL[32];
    __shared__ float w32[32];
    __shared__ float redsm[256];
    __shared__ float ratio_s;
    int b = blockIdx.x, j = threadIdx.x;
    int pix = xp[0] * 64 + yp[0];
    int p0 = b * 32;

    // ---- P1: cache rows, qt = qt_in + r128 @ E, scores, block max
    {
        const float4* mv = (const float4*)(mem + (long)p0 * 256);
        float4* sv = (float4*)sRow;
        for (int t = j; t < 2048; t += 256) sv[t] = mv[t];
    }
    if (j < 128) r128s[j] = __ldcg(&g_r128[j]);
    __syncthreads();

    {
        float acc = __ldcg(&g_qt_in[j]);
#pragma unroll 8
        for (int k = 0; k < 128; k++) acc += r128s[k] * g_E[k * 256 + j];
        qs[j] = acc;
    }
    __syncthreads();

    {
        int warp = j >> 5, lane = j & 31;
#pragma unroll
        for (int u = 0; u < 4; u++) {
            int p = warp * 4 + u;
            float acc = 0.f;
#pragma unroll
            for (int t = 0; t < 8; t++) acc += qs[lane + 32 * t] * sRow[p * 256 + lane + 32 * t];
#pragma unroll
            for (int off = 16; off; off >>= 1) acc += __shfl_down_sync(0xFFFFFFFFu, acc, off);
            if (lane == 0) scL[p] = acc;
        }
    }
    __syncthreads();
    if (j < 32) {
        float v = scL[j];
#pragma unroll
        for (int off = 16; off; off >>= 1) v = fmaxf(v, __shfl_down_sync(0xFFFFFFFFu, v, off));
        if (j == 0) atomicMax(&g_maxu, enc_f(v));
    }
    gbar();

    // ---- P2: exp/sumexp/ct from smem rows; blocks 8..15 compute rt chunks
    {
        float mx = dec_f(*(volatile unsigned*)&g_maxu);
        if (j < 32) w32[j] = expf(scL[j] - mx);
        __syncthreads();
        if (j < 32) {
            float v = w32[j];
#pragma unroll
            for (int off = 16; off; off >>= 1) v += __shfl_down_sync(0xFFFFFFFFu, v, off);
            if (j == 0) atomicAdd(&g_sumexp, v);
        }
        float acc = 0.f;
#pragma unroll
        for (int u = 0; u < 32; u++) acc += w32[u] * sRow[u * 256 + j];
        atomicAdd(&g_ct[j], acc);
    }
    if (b >= 8 && b < 16 && j < 32) {
        int jj = (b - 8) * 32 + j;
        float acc = 0.f;
#pragma unroll 16
        for (int k = 0; k < 128; k++) acc += r128s[k] * D2[k * 256 + jj];
        g_rt[jj] = acc;
    }
    gbar();
    if (b != 0) return;

    // ---- P3: epilogue (block 0)
    {
        float inv = 1.0f / *((volatile float*)&g_sumexp);
        float st = __ldcg(&g_st[j]);
        float ct = __ldcg(&g_ct[j]) * inv;
        float rt = __ldcg(&g_rt[j]);
        redsm[j] = st * ct;
        __syncthreads();
        for (int s = 128; s; s >>= 1) { if (j < s) redsm[j] += redsm[j + s]; __syncthreads(); }
        float local_imp = redsm[0];
        __syncthreads();
        redsm[j] = st * rt;
        __syncthreads();
        for (int s = 128; s; s >>= 1) { if (j < s) redsm[j] += redsm[j + s]; __syncthreads(); }
        if (j == 0) ratio_s = local_imp / (local_imp + redsm[0]);
        __syncthreads();
        float dval = __ldcg(&g_dp[j]) + __ldcg(&g_dp[256 + j]);
        out[j] = ct;
        out[256 + j] = rt;
        out[512 + (long)j * 4096 + pix] = mem[pix * 256 + j] + ratio_s * dval;
    }
}

// ---------------- launch ----------------
extern "C" void kernel_launch(void* const* d_in, const int* in_sizes, int n_in,
                              void* d_out, int out_size) {
    const float* inputs = (const float*)d_in[0];
    const float* memory = (const float*)d_in[1];
    const float* K1     = (const float*)d_in[2];
    const float* K2     = (const float*)d_in[3];
    const float* D1     = (const float*)d_in[4];
    const float* D2     = (const float*)d_in[5];
    const float* CK     = (const float*)d_in[6];
    const float* REC    = (const float*)d_in[7];
    const int*   xp     = (const int*)d_in[8];
    const int*   yp     = (const int*)d_in[9];
    float* out = (float*)d_out;

    static int smem_set = 0;
    if (!smem_set) {
        cudaFuncSetAttribute(conv2_kernel, cudaFuncAttributeMaxDynamicSharedMemorySize,
                             17536 * 4);
        smem_set = 1;
    }

    stage1_kernel<<<514, 256>>>(memory, K1, D2, CK, REC, inputs, out);
    conv2_kernel<<<dim3(62, 2), 256, 17536 * 4>>>(K2, REC, memory, xp, yp);
    gemv_kernel<<<466, 256>>>(D1);
    stage3_kernel<<<128, 256>>>(memory, D2, xp, yp, out);
}